// round 3
// baseline (speedup 1.0000x reference)
#include <cuda_runtime.h>

// Problem constants
#define BB 2
#define NN 200000
#define CC 16
#define DD 256
#define HH 256
#define WW 32
#define VV (DD * HH * WW)          // 2097152 = 2^21
#define LOGV 21

// Scratch, zero-initialized at module load. Invariant maintained by
// finalize_kernel: scratch is all-zero at entry of every kernel_launch.
// Layout: g_sums4[b][grp][v] = float4 holding channels 4*grp..4*grp+3 of voxel v.
__device__ float4 g_sums4[(size_t)BB * 4 * VV];
__device__ float  g_cnt[(size_t)BB * VV];        // [b][v]

__device__ __forceinline__ int voxel_idx(float p, float lo, float range, float dim, int dmax) {
    // Mirror reference exactly: (p - lo) / (hi - lo) * D, truncate, clamp
    float t = __fmul_rn(__fdiv_rn(__fsub_rn(p, lo), range), dim);
    int i = (int)t;                // trunc toward zero, matches astype(int32)
    i = i < 0 ? 0 : i;
    i = i > dmax ? dmax : i;
    return i;
}

__global__ void __launch_bounds__(256) scatter_kernel(const float* __restrict__ pts,
                                                      const float* __restrict__ fts) {
    int t = blockIdx.x * blockDim.x + threadIdx.x;
    if (t >= BB * NN) return;

    float x = pts[3 * t + 0];
    float y = pts[3 * t + 1];
    float z = pts[3 * t + 2];

    int vx = voxel_idx(x, -48.0f, 96.0f, 256.0f, DD - 1);
    int vy = voxel_idx(y, -48.0f, 96.0f, 256.0f, HH - 1);
    int vz = voxel_idx(z,  -4.0f,  5.5f,  32.0f, WW - 1);

    int flat = (vx * HH + vy) * WW + vz;
    int b = (t >= NN) ? 1 : 0;

    atomicAdd(&g_cnt[((size_t)b << LOGV) + flat], 1.0f);

    const float4* f = reinterpret_cast<const float4*>(fts + (size_t)t * CC);
#pragma unroll
    for (int grp = 0; grp < 4; grp++) {
        float4 v = f[grp];
        float4* s = &g_sums4[(((size_t)(b * 4 + grp)) << LOGV) + flat];
        asm volatile("red.global.add.v4.f32 [%0], {%1,%2,%3,%4};"
                     :: "l"(s), "f"(v.x), "f"(v.y), "f"(v.z), "f"(v.w)
                     : "memory");
    }
}

// 4x4 transpose within lane quads via shfl.bfly (2 stages).
__device__ __forceinline__ void quad_transpose(float4& s, int l) {
    // stage 1 (xor 1)
    float u0 = __shfl_xor_sync(0xffffffffu, (l & 1) ? s.x : s.y, 1);
    if (l & 1) s.x = u0; else s.y = u0;
    float u1 = __shfl_xor_sync(0xffffffffu, (l & 1) ? s.z : s.w, 1);
    if (l & 1) s.z = u1; else s.w = u1;
    // stage 2 (xor 2)
    float u2 = __shfl_xor_sync(0xffffffffu, (l & 2) ? s.x : s.z, 2);
    if (l & 2) s.x = u2; else s.z = u2;
    float u3 = __shfl_xor_sync(0xffffffffu, (l & 2) ? s.y : s.w, 2);
    if (l & 2) s.y = u3; else s.w = u3;
}

// One thread per voxel. All global accesses lane-contiguous (coalesced).
__global__ void __launch_bounds__(256) finalize_kernel(float* __restrict__ out) {
    int g = blockIdx.x * blockDim.x + threadIdx.x;   // global voxel id, 0..B*V-1
    int b = g >> LOGV;
    int v = g & (VV - 1);
    int l = threadIdx.x & 31;

    float c = g_cnt[g];
    bool ne = c > 0.0f;
    float r = ne ? __frcp_rn(c) : 0.0f;
    if (ne) g_cnt[g] = 0.0f;                          // predicated, coalesced

    const float4 z4 = make_float4(0.f, 0.f, 0.f, 0.f);
    // output base for this lane after transpose: channel 4*grp + (v&3), voxel v&~3
    float* obase = out + ((size_t)b * CC << LOGV) + (size_t)(v & ~3);

#pragma unroll
    for (int grp = 0; grp < 4; grp++) {
        float4* sp = &g_sums4[(((size_t)(b * 4 + grp)) << LOGV) + v];
        float4 s = z4;
        if (ne) {
            s = *sp;                                  // predicated coalesced LDG.128
            s.x *= r; s.y *= r; s.z *= r; s.w *= r;
            *sp = z4;                                 // predicated coalesced rezero
        }
        quad_transpose(s, l);                         // lane now holds ch 4*grp+(l&3), voxels (v&~3)..+3
        *reinterpret_cast<float4*>(obase + ((size_t)(4 * grp + (v & 3)) << LOGV)) = s;
    }
}

extern "C" void kernel_launch(void* const* d_in, const int* in_sizes, int n_in,
                              void* d_out, int out_size) {
    const float* pts = (const float*)d_in[0];   // [B,N,3] f32
    const float* fts = (const float*)d_in[1];   // [B,N,16] f32
    float* out = (float*)d_out;                 // [B,16,D,H,W] f32

    const int npts = BB * NN;
    scatter_kernel<<<(npts + 255) / 256, 256>>>(pts, fts);

    const int nvox = BB * VV;
    finalize_kernel<<<nvox / 256, 256>>>(out);
}

// round 4
// speedup vs baseline: 3.8687x; 3.8687x over previous
#include <cuda_runtime.h>

// Problem constants
#define BB 2
#define NN 200000
#define CC 16
#define DD 256
#define HH 256
#define WW 32
#define VV (DD * HH * WW)          // 2097152 = 2^21
#define LOGV 21

#define VOX_PER_BLOCK 512          // finalize: voxels per block (256 threads)

// Scratch: zero-initialized at module load. Invariant maintained by
// finalize_kernel: scratch is all-zero at entry of every kernel_launch.
__device__ float4 g_sums[(size_t)BB * VV * 4];   // [b][v][16ch] fp32, 4x float4 per voxel
__device__ float  g_cnt[(size_t)BB * VV];        // [b][v]

__device__ __forceinline__ int voxel_idx(float p, float lo, float range, float dim, int dmax) {
    // Mirror reference exactly: (p - lo) / (hi - lo) * D, truncate, clamp
    float t = __fmul_rn(__fdiv_rn(__fsub_rn(p, lo), range), dim);
    int i = (int)t;                // trunc toward zero, matches astype(int32)
    i = i < 0 ? 0 : i;
    i = i > dmax ? dmax : i;
    return i;
}

// ---- scatter: identical to the 98.4us round-1 kernel ----
__global__ void __launch_bounds__(256) scatter_kernel(const float* __restrict__ pts,
                                                      const float* __restrict__ fts) {
    int t = blockIdx.x * blockDim.x + threadIdx.x;
    if (t >= BB * NN) return;

    float x = pts[3 * t + 0];
    float y = pts[3 * t + 1];
    float z = pts[3 * t + 2];

    int vx = voxel_idx(x, -48.0f, 96.0f, 256.0f, DD - 1);
    int vy = voxel_idx(y, -48.0f, 96.0f, 256.0f, HH - 1);
    int vz = voxel_idx(z,  -4.0f,  5.5f,  32.0f, WW - 1);

    int flat = (vx * HH + vy) * WW + vz;
    int b = (t >= NN) ? 1 : 0;
    size_t g = ((size_t)b << LOGV) + (size_t)flat;

    atomicAdd(&g_cnt[g], 1.0f);

    const float4* f = reinterpret_cast<const float4*>(fts + (size_t)t * CC);
    float4* s = &g_sums[g * 4];
#pragma unroll
    for (int i = 0; i < 4; i++) {
        float4 v = f[i];
        asm volatile("red.global.add.v4.f32 [%0], {%1,%2,%3,%4};"
                     :: "l"(s + i), "f"(v.x), "f"(v.y), "f"(v.z), "f"(v.w)
                     : "memory");
    }
}

// ---- finalize: R1 load pattern + smem-staged transpose -> STG.128 output ----
__global__ void __launch_bounds__(256) finalize_kernel(float* __restrict__ out) {
    __shared__ float buf[CC * VOX_PER_BLOCK];     // 32 KB: [ch][vloc]

    const int tid = threadIdx.x;
    const int g0 = blockIdx.x * VOX_PER_BLOCK;    // first global voxel of block
    const int b  = g0 >> LOGV;
    const int v0 = g0 & (VV - 1);

    const float4 z4 = make_float4(0.f, 0.f, 0.f, 0.f);

    // Phase 1: each thread finalizes 2 voxels into smem (R1-proven access pattern).
#pragma unroll
    for (int j = 0; j < 2; j++) {
        int vloc = j * 256 + tid;
        int g = g0 + vloc;

        float c = g_cnt[g];
        bool ne = c > 0.0f;
        float r = ne ? __frcp_rn(c) : 0.0f;

        float4 a[4] = {z4, z4, z4, z4};
        if (ne) {
            float4* s = &g_sums[(size_t)g * 4];
#pragma unroll
            for (int i = 0; i < 4; i++) {
                float4 v = s[i];                  // predicated LDG.128, 64B lane stride (R1 pattern)
                v.x *= r; v.y *= r; v.z *= r; v.w *= r;
                a[i] = v;
                s[i] = z4;                        // re-zero scratch (dirty lines only)
            }
            g_cnt[g] = 0.0f;
        }

#pragma unroll
        for (int i = 0; i < 4; i++) {             // 16 conflict-free STS.32
            buf[(4 * i + 0) * VOX_PER_BLOCK + vloc] = a[i].x;
            buf[(4 * i + 1) * VOX_PER_BLOCK + vloc] = a[i].y;
            buf[(4 * i + 2) * VOX_PER_BLOCK + vloc] = a[i].z;
            buf[(4 * i + 3) * VOX_PER_BLOCK + vloc] = a[i].w;
        }
    }

    __syncthreads();

    // Phase 2: coalesced STG.128 of the transposed tile.
    // 16 ch * 128 quads = 2048 float4 = 8 iterations * 256 threads.
    float* ob = out + ((size_t)b * CC << LOGV) + v0;
#pragma unroll
    for (int i = 0; i < 8; i++) {
        int flat = i * 256 + tid;
        int ch = flat >> 7;                       // constant within a warp
        int q  = flat & 127;
        float4 v = *reinterpret_cast<const float4*>(&buf[ch * VOX_PER_BLOCK + 4 * q]);
        __stcs(reinterpret_cast<float4*>(ob + ((size_t)ch << LOGV) + 4 * q), v);
    }
}

extern "C" void kernel_launch(void* const* d_in, const int* in_sizes, int n_in,
                              void* d_out, int out_size) {
    const float* pts = (const float*)d_in[0];   // [B,N,3] f32
    const float* fts = (const float*)d_in[1];   // [B,N,16] f32
    float* out = (float*)d_out;                 // [B,16,D,H,W] f32

    const int npts = BB * NN;
    scatter_kernel<<<(npts + 255) / 256, 256>>>(pts, fts);

    const int nblocks = (BB * VV) / VOX_PER_BLOCK;
    finalize_kernel<<<nblocks, 256>>>(out);
}